// round 1
// baseline (speedup 1.0000x reference)
#include <cuda_runtime.h>
#include <math.h>

#define BB   8
#define LL   8192
#define DIM  512
#define NH   8
#define DH   64
#define KS   13
#define NS   6        // KS/2
#define DIL  2

// Scratch for Q,K,V in head-major layout [B, H, L, DH] (fp32)
__device__ float g_q[(size_t)BB * NH * LL * DH];
__device__ float g_k[(size_t)BB * NH * LL * DH];
__device__ float g_v[(size_t)BB * NH * LL * DH];

// ---------------------------------------------------------------------------
// Fused QKV projection: out_z = (hidden @ W_z + b_z) * scale_z
// A: [M=B*L, K=512] row-major.  W: [512, 512] row-major.
// Tile 128x128, BK=8, 256 threads, 8x8 micro-tile per thread, double-buffered.
// Epilogue scatters into head-major scratch [B,H,L,DH].
// ---------------------------------------------------------------------------
__global__ __launch_bounds__(256, 2)
void qkv_gemm_kernel(const float* __restrict__ A,
                     const float* __restrict__ Wq, const float* __restrict__ Wk,
                     const float* __restrict__ Wv,
                     const float* __restrict__ bq, const float* __restrict__ bk,
                     const float* __restrict__ bv)
{
    const int z = blockIdx.z;
    const float* W    = (z == 0) ? Wq : ((z == 1) ? Wk : Wv);
    const float* bias = (z == 0) ? bq : ((z == 1) ? bk : bv);
    float* out        = (z == 0) ? g_q : ((z == 1) ? g_k : g_v);
    const float scale = (z == 0) ? 0.125f : 1.0f;   // q /= sqrt(DH)=8

    __shared__ float As[2][8][128];
    __shared__ float Bs[2][8][128];

    const int t  = threadIdx.x;
    const int tx = t & 15;      // 0..15  -> column groups
    const int ty = t >> 4;      // 0..15  -> row groups
    const int m0 = blockIdx.x << 7;
    const int n0 = blockIdx.y << 7;

    // global->smem load mapping
    const int am  = t >> 1;          // 0..127 (A row within tile)
    const int ak  = (t & 1) * 4;     // 0 or 4 (A k offset)
    const int bk_ = t >> 5;          // 0..7   (B k row)
    const int bn  = (t & 31) * 4;    // 0..124 (B col)

    const float* Aptr = A + (size_t)(m0 + am) * DIM + ak;
    const float* Wptr = W + (size_t)bk_ * DIM + n0 + bn;

    float4 a_nx = *(const float4*)Aptr;
    float4 b_nx = *(const float4*)Wptr;

    As[0][ak + 0][am] = a_nx.x;
    As[0][ak + 1][am] = a_nx.y;
    As[0][ak + 2][am] = a_nx.z;
    As[0][ak + 3][am] = a_nx.w;
    *(float4*)&Bs[0][bk_][bn] = b_nx;
    __syncthreads();

    float acc[8][8];
    #pragma unroll
    for (int ii = 0; ii < 8; ++ii)
        #pragma unroll
        for (int jj = 0; jj < 8; ++jj) acc[ii][jj] = 0.f;

    const int KT = DIM / 8;   // 64 k-tiles
    for (int kt = 0; kt < KT; ++kt) {
        const int buf = kt & 1;
        if (kt < KT - 1) {
            a_nx = *(const float4*)(Aptr + (kt + 1) * 8);
            b_nx = *(const float4*)(Wptr + (size_t)(kt + 1) * 8 * DIM);
        }
        #pragma unroll
        for (int kk = 0; kk < 8; ++kk) {
            float4 a0 = *(const float4*)&As[buf][kk][ty * 4];
            float4 a1 = *(const float4*)&As[buf][kk][64 + ty * 4];
            float4 b0 = *(const float4*)&Bs[buf][kk][tx * 4];
            float4 b1 = *(const float4*)&Bs[buf][kk][64 + tx * 4];
            float ar[8] = {a0.x, a0.y, a0.z, a0.w, a1.x, a1.y, a1.z, a1.w};
            float br[8] = {b0.x, b0.y, b0.z, b0.w, b1.x, b1.y, b1.z, b1.w};
            #pragma unroll
            for (int ii = 0; ii < 8; ++ii)
                #pragma unroll
                for (int jj = 0; jj < 8; ++jj)
                    acc[ii][jj] = fmaf(ar[ii], br[jj], acc[ii][jj]);
        }
        if (kt < KT - 1) {
            const int nb = buf ^ 1;
            As[nb][ak + 0][am] = a_nx.x;
            As[nb][ak + 1][am] = a_nx.y;
            As[nb][ak + 2][am] = a_nx.z;
            As[nb][ak + 3][am] = a_nx.w;
            *(float4*)&Bs[nb][bk_][bn] = b_nx;
            __syncthreads();
        }
    }

    // Epilogue: add bias, scale, scatter to [B,H,L,DH]
    #pragma unroll
    for (int ii = 0; ii < 8; ++ii) {
        const int m  = m0 + ((ii < 4) ? (ty * 4 + ii) : (64 + ty * 4 + ii - 4));
        const int bb = m >> 13;          // / LL
        const int l  = m & (LL - 1);
        #pragma unroll
        for (int g = 0; g < 2; ++g) {
            const int n = n0 + ((g == 0) ? (tx * 4) : (64 + tx * 4));
            const float4 bv4 = *(const float4*)&bias[n];
            float4 r;
            r.x = (acc[ii][g * 4 + 0] + bv4.x) * scale;
            r.y = (acc[ii][g * 4 + 1] + bv4.y) * scale;
            r.z = (acc[ii][g * 4 + 2] + bv4.z) * scale;
            r.w = (acc[ii][g * 4 + 3] + bv4.w) * scale;
            const int hh = n >> 6;
            const int d  = n & 63;
            *(float4*)&out[(((size_t)bb * NH + hh) * LL + l) * DH + d] = r;
        }
    }
}

// ---------------------------------------------------------------------------
// NA1D attention (KS=13, DIL=2). One block = 128 queries of one (b,h).
// K tile staged in smem -> scores+softmax in regs; smem reused for V tile.
// Row pad 68 floats => conflict-free LDS.128 across consecutive rows.
// ---------------------------------------------------------------------------
#define QT   128
#define SPAN 152
#define PAD  68

__global__ __launch_bounds__(128, 4)
void na1d_kernel(const float* __restrict__ rpb, float* __restrict__ out)
{
    __shared__ float kv[SPAN][PAD];
    __shared__ float s_rpb[2 * KS - 1];

    const int tid = threadIdx.x;
    const int bh  = blockIdx.y;          // b*NH + h
    const int b   = bh >> 3;
    const int h   = bh & 7;
    const int l0  = blockIdx.x << 7;
    const int i   = l0 + tid;

    if (tid < 2 * KS - 1) s_rpb[tid] = rpb[h * (2 * KS - 1) + tid];

    // NATTEN dilated window-start / bias-start (DIL=2, L even so b=0 branch)
    int ws, ps;
    if (i < NS * DIL) {                  // i < 12
        ws = i & 1;
        ps = (KS - 1) - (i >> 1);
    } else if (i + NS * DIL >= LL) {     // i >= L-12
        ws = LL - KS * DIL + (i & 1);
        ps = (LL - 1 - i) >> 1;
    } else {
        ws = i - NS * DIL;
        ps = NS;
    }

    const int lo = (l0 >= NS * DIL) ? (l0 - NS * DIL) : 0;
    const int himax = l0 + QT - 1 + NS * DIL;
    const int hi = (himax <= LL - 1) ? himax : (LL - 1);
    const int nrows = hi - lo + 1;
    const int n4 = nrows * (DH / 4);
    const int r0 = ws - lo;

    const size_t base = (size_t)bh * LL * DH;

    // stage K tile
    {
        const float4* src = (const float4*)(g_k + base + (size_t)lo * DH);
        for (int tt = tid; tt < n4; tt += QT) {
            const int r = tt >> 4, c = tt & 15;
            *(float4*)&kv[r][c << 2] = src[tt];
        }
    }

    // q into registers
    float4 q[16];
    {
        const float4* qp = (const float4*)(g_q + base + (size_t)i * DH);
        #pragma unroll
        for (int d = 0; d < 16; ++d) q[d] = qp[d];
    }
    __syncthreads();

    // scores
    float sc[KS];
    #pragma unroll
    for (int j = 0; j < KS; ++j) {
        const float* kr = kv[r0 + DIL * j];
        float s = 0.f;
        #pragma unroll
        for (int d = 0; d < 16; ++d) {
            const float4 k4 = *(const float4*)&kr[d << 2];
            s = fmaf(q[d].x, k4.x, s);
            s = fmaf(q[d].y, k4.y, s);
            s = fmaf(q[d].z, k4.z, s);
            s = fmaf(q[d].w, k4.w, s);
        }
        sc[j] = s + s_rpb[ps + j];
    }

    // softmax (registers)
    float mx = sc[0];
    #pragma unroll
    for (int j = 1; j < KS; ++j) mx = fmaxf(mx, sc[j]);
    float sum = 0.f;
    #pragma unroll
    for (int j = 0; j < KS; ++j) { sc[j] = __expf(sc[j] - mx); sum += sc[j]; }
    const float rinv = 1.f / sum;

    __syncthreads();   // everyone done reading K tile

    // stage V tile (same buffer)
    {
        const float4* src = (const float4*)(g_v + base + (size_t)lo * DH);
        for (int tt = tid; tt < n4; tt += QT) {
            const int r = tt >> 4, c = tt & 15;
            *(float4*)&kv[r][c << 2] = src[tt];
        }
    }
    __syncthreads();

    // weighted sum of V
    float4 o[16];
    #pragma unroll
    for (int d = 0; d < 16; ++d) o[d] = make_float4(0.f, 0.f, 0.f, 0.f);

    #pragma unroll
    for (int j = 0; j < KS; ++j) {
        const float p = sc[j];
        const float* vr = kv[r0 + DIL * j];
        #pragma unroll
        for (int d = 0; d < 16; ++d) {
            const float4 v4 = *(const float4*)&vr[d << 2];
            o[d].x = fmaf(p, v4.x, o[d].x);
            o[d].y = fmaf(p, v4.y, o[d].y);
            o[d].z = fmaf(p, v4.z, o[d].z);
            o[d].w = fmaf(p, v4.w, o[d].w);
        }
    }

    // write out [B, L, H*DH]
    float* op = out + ((size_t)b * LL + i) * DIM + h * DH;
    #pragma unroll
    for (int d = 0; d < 16; ++d) {
        float4 r = o[d];
        r.x *= rinv; r.y *= rinv; r.z *= rinv; r.w *= rinv;
        *(float4*)&op[d << 2] = r;
    }
}

// ---------------------------------------------------------------------------
extern "C" void kernel_launch(void* const* d_in, const int* in_sizes, int n_in,
                              void* d_out, int out_size)
{
    const float* hs  = (const float*)d_in[0];
    const float* Wq  = (const float*)d_in[1];
    const float* bq  = (const float*)d_in[2];
    const float* Wk  = (const float*)d_in[3];
    const float* bk  = (const float*)d_in[4];
    const float* Wv  = (const float*)d_in[5];
    const float* bv  = (const float*)d_in[6];
    const float* rpb = (const float*)d_in[7];
    float* out = (float*)d_out;

    dim3 gGemm(BB * LL / 128, DIM / 128, 3);   // (512, 4, 3)
    qkv_gemm_kernel<<<gGemm, 256>>>(hs, Wq, Wk, Wv, bq, bk, bv);

    dim3 gAttn(LL / QT, BB * NH);              // (64, 64)
    na1d_kernel<<<gAttn, 128>>>(rpb, out);
}

// round 3
// speedup vs baseline: 2.1873x; 2.1873x over previous
#include <cuda_runtime.h>
#include <cuda_bf16.h>
#include <cstdint>

#define BB   8
#define LL   8192
#define DIM  512
#define NH   8
#define DH   64
#define KS   13
#define NS   6
#define DIL  2

// ---------------------------------------------------------------------------
// Device scratch (static only)
// ---------------------------------------------------------------------------
__device__ float g_q[(size_t)BB * NH * LL * DH];
__device__ float g_k[(size_t)BB * NH * LL * DH];
__device__ float g_v[(size_t)BB * NH * LL * DH];
__device__ __nv_bfloat16 g_ah[(size_t)BB * LL * DIM];   // hidden hi split [M,K]
__device__ __nv_bfloat16 g_al[(size_t)BB * LL * DIM];   // hidden lo split
__device__ __nv_bfloat16 g_wh[3][DIM * DIM];            // W^T hi  [N,K]
__device__ __nv_bfloat16 g_wl[3][DIM * DIM];            // W^T lo  [N,K]

// ---------------------------------------------------------------------------
// Baseline-PTX helpers (all sm_80-level, assemble on plain sm_103)
// ---------------------------------------------------------------------------
__device__ __forceinline__ uint32_t smem_u32(const void* p) {
    uint32_t a;
    asm("{ .reg .u64 t; cvta.to.shared.u64 t, %1; cvt.u32.u64 %0, t; }" : "=r"(a) : "l"(p));
    return a;
}
__device__ __forceinline__ void cp_async16(uint32_t saddr, const void* gptr) {
    asm volatile("cp.async.cg.shared.global [%0], [%1], 16;"
                 :: "r"(saddr), "l"(__cvta_generic_to_global(gptr)) : "memory");
}
#define CP_COMMIT() asm volatile("cp.async.commit_group;" ::: "memory")
#define CP_WAIT(n)  asm volatile("cp.async.wait_group %0;" :: "n"(n) : "memory")

__device__ __forceinline__ void ldsm_x4(uint32_t* r, uint32_t addr) {
    asm volatile("ldmatrix.sync.aligned.m8n8.x4.shared.b16 {%0,%1,%2,%3}, [%4];"
                 : "=r"(r[0]), "=r"(r[1]), "=r"(r[2]), "=r"(r[3]) : "r"(addr));
}
__device__ __forceinline__ void ldsm_x2(uint32_t* r, uint32_t addr) {
    asm volatile("ldmatrix.sync.aligned.m8n8.x2.shared.b16 {%0,%1}, [%2];"
                 : "=r"(r[0]), "=r"(r[1]) : "r"(addr));
}
__device__ __forceinline__ void mma16816(float* c, const uint32_t* a, const uint32_t* b) {
    asm volatile("mma.sync.aligned.m16n8k16.row.col.f32.bf16.bf16.f32 "
                 "{%0,%1,%2,%3}, {%4,%5,%6,%7}, {%8,%9}, {%0,%1,%2,%3};"
                 : "+f"(c[0]), "+f"(c[1]), "+f"(c[2]), "+f"(c[3])
                 : "r"(a[0]), "r"(a[1]), "r"(a[2]), "r"(a[3]), "r"(b[0]), "r"(b[1]));
}

// ---------------------------------------------------------------------------
// Split hidden states fp32 -> bf16 hi/lo
// ---------------------------------------------------------------------------
__global__ void convert_a_kernel(const float* __restrict__ A) {
    size_t i = ((size_t)blockIdx.x * 256 + threadIdx.x) * 4;
    float4 x = *(const float4*)(A + i);
    __nv_bfloat16 h0 = __float2bfloat16(x.x), h1 = __float2bfloat16(x.y);
    __nv_bfloat16 h2 = __float2bfloat16(x.z), h3 = __float2bfloat16(x.w);
    __nv_bfloat16 l0 = __float2bfloat16(x.x - __bfloat162float(h0));
    __nv_bfloat16 l1 = __float2bfloat16(x.y - __bfloat162float(h1));
    __nv_bfloat16 l2 = __float2bfloat16(x.z - __bfloat162float(h2));
    __nv_bfloat16 l3 = __float2bfloat16(x.w - __bfloat162float(h3));
    union { __nv_bfloat16 b[4]; uint2 u; } ph, pl;
    ph.b[0] = h0; ph.b[1] = h1; ph.b[2] = h2; ph.b[3] = h3;
    pl.b[0] = l0; pl.b[1] = l1; pl.b[2] = l2; pl.b[3] = l3;
    *(uint2*)(g_ah + i) = ph.u;
    *(uint2*)(g_al + i) = pl.u;
}

// ---------------------------------------------------------------------------
// Transpose + split W [K,N] -> W^T [N,K] bf16 hi/lo
// ---------------------------------------------------------------------------
__global__ void convert_w_kernel(const float* __restrict__ Wq,
                                 const float* __restrict__ Wk,
                                 const float* __restrict__ Wv) {
    const int z = blockIdx.z;
    const float* W = (z == 0) ? Wq : ((z == 1) ? Wk : Wv);
    __shared__ float t[32][33];
    const int n0 = blockIdx.x * 32, k0 = blockIdx.y * 32;
    #pragma unroll
    for (int j = 0; j < 32; j += 8)
        t[threadIdx.y + j][threadIdx.x] = W[(size_t)(k0 + threadIdx.y + j) * DIM + n0 + threadIdx.x];
    __syncthreads();
    #pragma unroll
    for (int j = 0; j < 32; j += 8) {
        float v = t[threadIdx.x][threadIdx.y + j];
        __nv_bfloat16 h = __float2bfloat16(v);
        __nv_bfloat16 l = __float2bfloat16(v - __bfloat162float(h));
        size_t o = (size_t)(n0 + threadIdx.y + j) * DIM + k0 + threadIdx.x;
        g_wh[z][o] = h;
        g_wl[z][o] = l;
    }
}

// ---------------------------------------------------------------------------
// HMMA bf16 GEMM (3-term split): C = Ah*Bh + Ah*Bl + Al*Bh, fp32 accum.
// CTA tile 128(M) x 128(N), BK=64, 256 threads, double-buffered cp.async.
// smem per stage: Ah | Al | Bh | Bl, each 128x64 bf16 (16KB), XOR-swizzled.
// ---------------------------------------------------------------------------
#define TILE_B   16384
#define STAGE_B  (4 * TILE_B)     // 64KB

__global__ void __launch_bounds__(256, 1)
qkv_mma_gemm(const float* __restrict__ bq, const float* __restrict__ bk,
             const float* __restrict__ bv)
{
    extern __shared__ __align__(1024) char dsm[];
    __shared__ float s_bias[128];

    const int tid  = threadIdx.x;
    const int wid  = tid >> 5;
    const int lane = tid & 31;
    const int wm   = wid >> 2;       // 0..1  (64-row slabs)
    const int wn   = wid & 3;        // 0..3  (32-col slabs)
    const int nt   = blockIdx.x & 3;
    const int z    = blockIdx.x >> 2;
    const int mt   = blockIdx.y;

    const uint32_t sbase = smem_u32(dsm);

    const float* bias = (z == 0) ? bq : ((z == 1) ? bk : bv);
    const float scale = (z == 0) ? 0.125f : 1.0f;
    float* outp       = (z == 0) ? g_q : ((z == 1) ? g_k : g_v);
    const __nv_bfloat16* srcs[4] = { g_ah + (size_t)mt * 128 * DIM,
                                     g_al + (size_t)mt * 128 * DIM,
                                     g_wh[z] + (size_t)nt * 128 * DIM,
                                     g_wl[z] + (size_t)nt * 128 * DIM };

    if (tid < 128) s_bias[tid] = bias[nt * 128 + tid];

    // ---- stage loader: 4 tiles, 128 rows x 8 sixteen-byte chunks each ----
    auto load_stage = [&](int kt, int buf) {
        const uint32_t sb = sbase + (uint32_t)buf * STAGE_B;
        #pragma unroll
        for (int tile = 0; tile < 4; ++tile) {
            const __nv_bfloat16* src = srcs[tile] + kt * 64;
            #pragma unroll
            for (int it = 0; it < 4; ++it) {
                const int c = it * 256 + tid;
                const int r = c >> 3, j = c & 7;
                const uint32_t soff = sb + (uint32_t)tile * TILE_B +
                                      (uint32_t)r * 128 + (uint32_t)((j ^ (r & 7)) << 4);
                cp_async16(soff, src + (size_t)r * DIM + j * 8);
            }
        }
        CP_COMMIT();
    };

    float acc[4][4][4];
    #pragma unroll
    for (int mi = 0; mi < 4; ++mi)
        #pragma unroll
        for (int ni = 0; ni < 4; ++ni)
            #pragma unroll
            for (int q = 0; q < 4; ++q) acc[mi][ni][q] = 0.f;

    load_stage(0, 0);

    for (int kt = 0; kt < 8; ++kt) {
        if (kt < 7) load_stage(kt + 1, (kt + 1) & 1);
        if (kt < 7) { CP_WAIT(1); } else { CP_WAIT(0); }
        __syncthreads();

        const uint32_t sb = sbase + (uint32_t)(kt & 1) * STAGE_B;
        const uint32_t aH = sb, aL = sb + TILE_B, bH = sb + 2 * TILE_B, bL = sb + 3 * TILE_B;

        // ldmatrix address row components
        const int arow = wm * 64 + (lane & 15);       // + mi*16
        const int ahalf = lane >> 4;                  // k-chunk half for A
        const int brow = wn * 32 + (lane & 7);        // + ni*8
        const int bhalf = (lane >> 3) & 1;            // k-chunk half for B

        #pragma unroll
        for (int ks = 0; ks < 4; ++ks) {
            uint32_t bhf[4][2], blf[4][2];
            #pragma unroll
            for (int ni = 0; ni < 4; ++ni) {
                const int r = brow + ni * 8;
                const int j = ks * 2 + bhalf;
                const uint32_t off = (uint32_t)r * 128 + (uint32_t)((j ^ (r & 7)) << 4);
                ldsm_x2(bhf[ni], bH + off);
                ldsm_x2(blf[ni], bL + off);
            }
            #pragma unroll
            for (int mi = 0; mi < 4; ++mi) {
                const int r = arow + mi * 16;
                const int j = ks * 2 + ahalf;
                const uint32_t off = (uint32_t)r * 128 + (uint32_t)((j ^ (r & 7)) << 4);
                uint32_t ahf[4], alf[4];
                ldsm_x4(ahf, aH + off);
                ldsm_x4(alf, aL + off);
                #pragma unroll
                for (int ni = 0; ni < 4; ++ni) {
                    mma16816(acc[mi][ni], ahf, bhf[ni]);
                    mma16816(acc[mi][ni], ahf, blf[ni]);
                    mma16816(acc[mi][ni], alf, bhf[ni]);
                }
            }
        }
        __syncthreads();
    }

    // ---- epilogue: bias + scale, scatter to head-major [B,H,L,DH] ----
    const int g = lane >> 2, tig = lane & 3;
    #pragma unroll
    for (int mi = 0; mi < 4; ++mi) {
        #pragma unroll
        for (int half = 0; half < 2; ++half) {
            const int m = mt * 128 + wm * 64 + mi * 16 + g + half * 8;
            const int b = m >> 13;
            const int l = m & (LL - 1);
            #pragma unroll
            for (int ni = 0; ni < 4; ++ni) {
                const int nl = wn * 32 + ni * 8 + 2 * tig;
                const int n  = nt * 128 + nl;
                const int h  = n >> 6, d = n & 63;
                float2 r2;
                r2.x = (acc[mi][ni][half * 2 + 0] + s_bias[nl + 0]) * scale;
                r2.y = (acc[mi][ni][half * 2 + 1] + s_bias[nl + 1]) * scale;
                *(float2*)&outp[(((size_t)b * NH + h) * LL + l) * DH + d] = r2;
            }
        }
    }
}

// ---------------------------------------------------------------------------
// NA1D attention (unchanged — 195us)
// ---------------------------------------------------------------------------
#define QT   128
#define SPAN 152
#define PAD  68

__global__ void __launch_bounds__(128, 4)
na1d_kernel(const float* __restrict__ rpb, float* __restrict__ out)
{
    __shared__ float kv[SPAN][PAD];
    __shared__ float s_rpb[2 * KS - 1];

    const int tid = threadIdx.x;
    const int bh  = blockIdx.y;
    const int b   = bh >> 3;
    const int h   = bh & 7;
    const int l0  = blockIdx.x << 7;
    const int i   = l0 + tid;

    if (tid < 2 * KS - 1) s_rpb[tid] = rpb[h * (2 * KS - 1) + tid];

    int ws, ps;
    if (i < NS * DIL) {
        ws = i & 1;
        ps = (KS - 1) - (i >> 1);
    } else if (i + NS * DIL >= LL) {
        ws = LL - KS * DIL + (i & 1);
        ps = (LL - 1 - i) >> 1;
    } else {
        ws = i - NS * DIL;
        ps = NS;
    }

    const int lo = (l0 >= NS * DIL) ? (l0 - NS * DIL) : 0;
    const int himax = l0 + QT - 1 + NS * DIL;
    const int hi = (himax <= LL - 1) ? himax : (LL - 1);
    const int n4 = (hi - lo + 1) * (DH / 4);
    const int r0 = ws - lo;
    const size_t base = (size_t)bh * LL * DH;

    {
        const float4* src = (const float4*)(g_k + base + (size_t)lo * DH);
        for (int tt = tid; tt < n4; tt += QT) {
            const int r = tt >> 4, c = tt & 15;
            *(float4*)&kv[r][c << 2] = src[tt];
        }
    }
    float4 q[16];
    {
        const float4* qp = (const float4*)(g_q + base + (size_t)i * DH);
        #pragma unroll
        for (int d = 0; d < 16; ++d) q[d] = qp[d];
    }
    __syncthreads();

    float sc[KS];
    #pragma unroll
    for (int j = 0; j < KS; ++j) {
        const float* kr = kv[r0 + DIL * j];
        float s = 0.f;
        #pragma unroll
        for (int d = 0; d < 16; ++d) {
            const float4 k4 = *(const float4*)&kr[d << 2];
            s = fmaf(q[d].x, k4.x, s);
            s = fmaf(q[d].y, k4.y, s);
            s = fmaf(q[d].z, k4.z, s);
            s = fmaf(q[d].w, k4.w, s);
        }
        sc[j] = s + s_rpb[ps + j];
    }

    float mx = sc[0];
    #pragma unroll
    for (int j = 1; j < KS; ++j) mx = fmaxf(mx, sc[j]);
    float sum = 0.f;
    #pragma unroll
    for (int j = 0; j < KS; ++j) { sc[j] = __expf(sc[j] - mx); sum += sc[j]; }
    const float rinv = 1.f / sum;

    __syncthreads();

    {
        const float4* src = (const float4*)(g_v + base + (size_t)lo * DH);
        for (int tt = tid; tt < n4; tt += QT) {
            const int r = tt >> 4, c = tt & 15;
            *(float4*)&kv[r][c << 2] = src[tt];
        }
    }
    __syncthreads();

    float4 o[16];
    #pragma unroll
    for (int d = 0; d < 16; ++d) o[d] = make_float4(0.f, 0.f, 0.f, 0.f);

    #pragma unroll
    for (int j = 0; j < KS; ++j) {
        const float p = sc[j];
        const float* vr = kv[r0 + DIL * j];
        #pragma unroll
        for (int d = 0; d < 16; ++d) {
            const float4 v4 = *(const float4*)&vr[d << 2];
            o[d].x = fmaf(p, v4.x, o[d].x);
            o[d].y = fmaf(p, v4.y, o[d].y);
            o[d].z = fmaf(p, v4.z, o[d].z);
            o[d].w = fmaf(p, v4.w, o[d].w);
        }
    }

    float* op = out + ((size_t)b * LL + i) * DIM + h * DH;
    #pragma unroll
    for (int d = 0; d < 16; ++d) {
        float4 r = o[d];
        r.x *= rinv; r.y *= rinv; r.z *= rinv; r.w *= rinv;
        *(float4*)&op[d << 2] = r;
    }
}

// ---------------------------------------------------------------------------
extern "C" void kernel_launch(void* const* d_in, const int* in_sizes, int n_in,
                              void* d_out, int out_size)
{
    const float* hs  = (const float*)d_in[0];
    const float* Wq  = (const float*)d_in[1];
    const float* bq  = (const float*)d_in[2];
    const float* Wk  = (const float*)d_in[3];
    const float* bk  = (const float*)d_in[4];
    const float* Wv  = (const float*)d_in[5];
    const float* bv  = (const float*)d_in[6];
    const float* rpb = (const float*)d_in[7];
    float* out = (float*)d_out;

    const int dyn_smem = 2 * STAGE_B;   // 128KB
    cudaFuncSetAttribute(qkv_mma_gemm, cudaFuncAttributeMaxDynamicSharedMemorySize, dyn_smem);

    convert_a_kernel<<<32768, 256>>>(hs);
    convert_w_kernel<<<dim3(16, 16, 3), dim3(32, 8)>>>(Wq, Wk, Wv);
    qkv_mma_gemm<<<dim3(12, 512), 256, dyn_smem>>>(bq, bk, bv);
    na1d_kernel<<<dim3(LL / QT, BB * NH), 128>>>(rpb, out);
}